// round 2
// baseline (speedup 1.0000x reference)
#include <cuda_runtime.h>
#include <cuda_bf16.h>

#define NB   32
#define NT   512
#define ND   768
#define NK   256
#define NKP1 257
#define NH   512
#define NP   769          // NKP1 + NH
#define NCTA 128
#define NPACK (128*769*16)

// ---------------- device scratch (static; no cudaMalloc allowed) ----------
__device__ float g_S[(size_t)NB*NT*NT];    // gram -> (in place) softmax weights
__device__ float g_wc[NB*NT];              // precomputed confidence readout
__device__ float g_Mk[(size_t)NB*NT*NK];   // memory keys, layout [b][t][k]
__device__ float g_Wpack[NPACK];           // per-CTA packed LSTM weights
__device__ float g_hT[2*NH*NB];            // double-buffered h, layout [j][b]
__device__ float g_hB[NB*NH];              // h, layout [b][j]
__device__ float g_keyrT[NKP1*NB];         // key_r, layout [k][b]
__device__ unsigned g_cnt;
__device__ volatile unsigned g_rel;

__device__ __forceinline__ float sigmf(float x) { return 1.f / (1.f + __expf(-x)); }

__device__ __forceinline__ void grid_bar(unsigned gen) {
    __threadfence();
    __syncthreads();
    if (threadIdx.x == 0) {
        unsigned arr = atomicAdd(&g_cnt, 1u) + 1u;
        if (arr == gen * (unsigned)NCTA) {
            __threadfence();
            g_rel = gen;
        } else {
            while (g_rel < gen) { }
        }
    }
    __syncthreads();
}

// ---------------- init: zero recurrent state + barrier ---------------------
__global__ void k_init() {
    int i = blockIdx.x * blockDim.x + threadIdx.x;
    if (i < 2*NH*NB) g_hT[i] = 0.f;
    if (i < NKP1*NB) g_keyrT[i] = 0.f;
    if (i == 0) { g_cnt = 0u; g_rel = 0u; }
}

// ---------------- weight pack: Wpack[ct][p][cl] ----------------------------
// CTA ct owns j in [ct*4, ct*4+4); cl = gate*4 + jj; col = gate*512 + ct*4 + jj
__global__ void k_pack(const float* __restrict__ Wx, const float* __restrict__ Wh) {
    int idx = blockIdx.x * blockDim.x + threadIdx.x;
    if (idx >= NPACK) return;
    int cl = idx & 15;
    int r  = idx >> 4;
    int p  = r % NP;
    int ct = r / NP;
    int jj = cl & 3, gate = cl >> 2;
    int col = gate * NH + ct * 4 + jj;
    float v = (p < NKP1) ? Wx[(size_t)p * 2048 + col]
                         : Wh[(size_t)(p - NKP1) * 2048 + col];
    g_Wpack[idx] = v;
}

// ---------------- gram: S[b][t][t'] = x_t . x_t'  (lower triangle) ---------
__global__ void k_gram(const float* __restrict__ x) {
    __shared__ float sa[64][17];
    __shared__ float sb[64][17];
    int bx = blockIdx.x;
    int b = bx / 36, pr = bx % 36;
    int ti = 0;
    while ((ti + 1) * (ti + 2) / 2 <= pr) ti++;
    int tj = pr - ti * (ti + 1) / 2;
    int tid = threadIdx.x;
    int ry = tid >> 4, rx = tid & 15;
    float acc[4][4] = {};
    const float* xa = x + ((size_t)b * NT + ti * 64) * ND;
    const float* xb = x + ((size_t)b * NT + tj * 64) * ND;
    for (int d0 = 0; d0 < ND; d0 += 16) {
        __syncthreads();
        for (int i = tid; i < 64 * 16; i += 256) {
            int r = i >> 4, c = i & 15;
            sa[r][c] = xa[(size_t)r * ND + d0 + c];
            sb[r][c] = xb[(size_t)r * ND + d0 + c];
        }
        __syncthreads();
#pragma unroll
        for (int dd = 0; dd < 16; ++dd) {
            float av[4], bv[4];
#pragma unroll
            for (int i = 0; i < 4; i++) av[i] = sa[ry * 4 + i][dd];
#pragma unroll
            for (int j = 0; j < 4; j++) bv[j] = sb[rx * 4 + j][dd];
#pragma unroll
            for (int i = 0; i < 4; i++)
#pragma unroll
                for (int j = 0; j < 4; j++) acc[i][j] += av[i] * bv[j];
        }
    }
#pragma unroll
    for (int i = 0; i < 4; i++) {
        int row = ti * 64 + ry * 4 + i;
        float* dst = &g_S[((size_t)b * NT + row) * NT + tj * 64 + rx * 4];
#pragma unroll
        for (int j = 0; j < 4; j++) dst[j] = acc[i][j];
    }
}

// ---------------- row softmax over t' < t, + wc ----------------------------
__global__ void k_softmax(const float* __restrict__ cgain, const float* __restrict__ cbias) {
    int bx = blockIdx.x;
    int t = bx & (NT - 1), b = bx >> 9;
    int tid = threadIdx.x;
    if (t == 0) { if (tid == 0) g_wc[b * NT] = 0.f; return; }
    float* row = &g_S[((size_t)b * NT + t) * NT];
    __shared__ float sred[4];
    __shared__ float sbuf[NT];
    float gain = cgain[0], bias = cbias[0];

    float m = -3.4e38f;
    for (int i = tid; i < t; i += 128) m = fmaxf(m, row[i]);
#pragma unroll
    for (int o = 16; o; o >>= 1) m = fmaxf(m, __shfl_xor_sync(~0u, m, o));
    if ((tid & 31) == 0) sred[tid >> 5] = m;
    __syncthreads();
    m = fmaxf(fmaxf(sred[0], sred[1]), fmaxf(sred[2], sred[3]));

    float s = 0.f;
    for (int i = tid; i < t; i += 128) { float e = __expf(row[i] - m); sbuf[i] = e; s += e; }
#pragma unroll
    for (int o = 16; o; o >>= 1) s += __shfl_xor_sync(~0u, s, o);
    __syncthreads();
    if ((tid & 31) == 0) sred[tid >> 5] = s;
    __syncthreads();
    s = sred[0] + sred[1] + sred[2] + sred[3];
    float inv = 1.f / s;

    float wca = 0.f;
    for (int i = tid; i < t; i += 128) {
        float sim = row[i];
        float w = sbuf[i] * inv;
        row[i] = w;
        wca += w * sigmf(sim * gain + bias);
    }
#pragma unroll
    for (int o = 16; o; o >>= 1) wca += __shfl_xor_sync(~0u, wca, o);
    __syncthreads();
    if ((tid & 31) == 0) sred[tid >> 5] = wca;
    __syncthreads();
    if (tid == 0) g_wc[b * NT + t] = sred[0] + sred[1] + sred[2] + sred[3];
}

// ---------------- persistent recurrence kernel -----------------------------
// smem layout (floats): sAct[24608] | red[8736] | zbuf[528]
// phase-2 aliases into red: sh[512] | sWrow[512] | redk[320] | sgm[1]
#define SM_SACT 24608
#define SM_RED  8736
#define SM_ZBUF 528
#define SM_FLOATS (SM_SACT + SM_RED + SM_ZBUF)

__global__ void __launch_bounds__(256, 1) k_rec(
    const float* __restrict__ b_lstm, const float* __restrict__ W_key,
    const float* __restrict__ b_key,  const float* __restrict__ W_g,
    const float* __restrict__ b_g,    float* __restrict__ out)
{
    extern __shared__ float sm[];
    float* sAct  = sm;
    float* red   = sm + SM_SACT;
    float* zbuf  = red + SM_RED;
    float* sh    = red;
    float* sWrow = red + 512;
    float* redk  = red + 1024;
    float* sgm   = red + 1344;

    const int ct = blockIdx.x, tid = threadIdx.x;
    const int cl = tid & 15, chunk = tid >> 4;
    const int p0 = chunk * 48;
    const int pe = (chunk == 15) ? NP : p0 + 48;
    const float* wp = g_Wpack + ((size_t)ct * NP) * 16 + cl;
    const int j0 = ct * 4;
    const int b2 = ct >> 2, kq = ct & 3, k0 = kq * 64;
    const int kl = tid & 63, qq = tid >> 6;
    float creg = 0.f;
    unsigned gen = 0;

    for (int t = 0; t < NT; ++t) {
        const int par = t & 1;
        // ---- stage activations into smem [p][b]
        {
            const float4* s1 = (const float4*)g_keyrT;
            const float4* s2 = (const float4*)(g_hT + par * (NH * NB));
            float4* d1 = (float4*)sAct;
            float4* d2 = d1 + 2056;
            for (int i = tid; i < 2056; i += 256) d1[i] = __ldcg(s1 + i);
            for (int i = tid; i < 4096; i += 256) d2[i] = __ldcg(s2 + i);
        }
        __syncthreads();
        // ---- LSTM GEMM slice: 16 cols x 32 batches, inner chunk
        float acc[32];
#pragma unroll
        for (int i = 0; i < 32; i++) acc[i] = 0.f;
#pragma unroll 2
        for (int p = p0; p < pe; ++p) {
            float w = wp[(size_t)p * 16];
            const float4* a4 = (const float4*)(sAct + p * 32);
#pragma unroll
            for (int q8 = 0; q8 < 8; ++q8) {
                float4 a = a4[q8];
                acc[q8 * 4 + 0] += w * a.x;
                acc[q8 * 4 + 1] += w * a.y;
                acc[q8 * 4 + 2] += w * a.z;
                acc[q8 * 4 + 3] += w * a.w;
            }
        }
#pragma unroll
        for (int b = 0; b < 32; b++) red[b * 273 + cl * 17 + chunk] = acc[b];
        __syncthreads();
        // ---- reduce across 16 chunks + bias
        for (int o = tid; o < 512; o += 256) {
            int c = o >> 5, b = o & 31;
            const float* rr = &red[b * 273 + c * 17];
            float s = 0.f;
#pragma unroll
            for (int ch = 0; ch < 16; ++ch) s += rr[ch];
            int gate = c >> 2, jj = c & 3;
            s += __ldg(&b_lstm[gate * NH + j0 + jj]);
            zbuf[c * 33 + b] = s;
        }
        __syncthreads();
        // ---- gate math; c-state register-resident in owner thread
        if (tid < 128) {
            int jj = tid >> 5, b = tid & 31;
            float zi = zbuf[(0 + jj) * 33 + b];
            float zf = zbuf[(4 + jj) * 33 + b];
            float zc = zbuf[(8 + jj) * 33 + b];
            float zo = zbuf[(12 + jj) * 33 + b];
            float ig = sigmf(zi), fg = sigmf(zf);
            float gc = tanhf(zc), og = sigmf(zo);
            creg = fg * creg + ig * gc;
            float hv = og * tanhf(creg);
            int j = j0 + jj;
            __stcg(&g_hT[(par ^ 1) * (NH * NB) + j * NB + b], hv);
            __stcg(&g_hB[b * NH + j], hv);
            if (t == NT - 1) out[b * NH + j] = hv;
        }
        if (t == NT - 1) break;
        grid_bar(++gen);

        // ================= phase 2: CTA = (b2, k-quarter) ==================
        {
            const float4* src = (const float4*)(g_hB + b2 * NH);
            float4* dst = (float4*)sh;
            if (tid < 128) dst[tid] = __ldcg(src + tid);
        }
        for (int i = tid; i < t; i += 256)
            sWrow[i] = __ldcg(&g_S[((size_t)b2 * NT + t) * NT + i]);
        __syncthreads();
        // gate scalar g = sigmoid(h . W_g + b_g)
        float pg = sh[tid] * __ldg(&W_g[tid]) + sh[tid + 256] * __ldg(&W_g[tid + 256]);
#pragma unroll
        for (int o = 16; o; o >>= 1) pg += __shfl_xor_sync(~0u, pg, o);
        if ((tid & 31) == 0) redk[tid >> 5] = pg;
        __syncthreads();
        if (tid == 0) {
            float s = 0.f;
            for (int i = 0; i < 8; i++) s += redk[i];
            sgm[0] = sigmf(s + __ldg(&b_g[0]));
        }
        __syncthreads();
        float gv = sgm[0];
        // key_w = h . W_key (64 cols per CTA, 4-way inner split)
        float kacc = 0.f;
        {
            const float* wk = W_key + (size_t)(qq * 128) * NK + k0 + kl;
            const float* shq = sh + qq * 128;
#pragma unroll 4
            for (int p = 0; p < 128; ++p) kacc += shq[p] * __ldg(&wk[(size_t)p * NK]);
        }
        __syncthreads();
        redk[kl * 5 + qq] = kacc;
        __syncthreads();
        if (tid < 64) {
            float kw = redk[tid * 5] + redk[tid * 5 + 1] + redk[tid * 5 + 2] + redk[tid * 5 + 3]
                     + __ldg(&b_key[k0 + tid]);
            __stcg(&g_Mk[((size_t)b2 * NT + t) * NK + k0 + tid], kw);
        }
        // attention readout: key_r[k] = g * sum_{t'<t} W[t,t'] * Mk[t'][k]
        float aacc = 0.f;
        if (t > 0) {
            const float* mkp = g_Mk + ((size_t)b2 * NT) * NK + k0 + kl;
#pragma unroll 4
            for (int t2 = qq; t2 < t; t2 += 4)
                aacc += sWrow[t2] * __ldcg(&mkp[(size_t)t2 * NK]);
        }
        __syncthreads();
        redk[kl * 5 + qq] = aacc;
        __syncthreads();
        if (tid < 64) {
            float kr = (t > 0)
                ? gv * (redk[tid * 5] + redk[tid * 5 + 1] + redk[tid * 5 + 2] + redk[tid * 5 + 3])
                : 0.f;
            __stcg(&g_keyrT[(k0 + tid) * NB + b2], kr);
        }
        if (tid == 64 && kq == 0) {
            float kr = (t > 0) ? gv * __ldg(&g_wc[b2 * NT + t]) : 0.f;
            __stcg(&g_keyrT[NK * NB + b2], kr);
        }
        grid_bar(++gen);
    }
}

// ---------------- launch ---------------------------------------------------
extern "C" void kernel_launch(void* const* d_in, const int* in_sizes, int n_in,
                              void* d_out, int out_size) {
    const float* x      = (const float*)d_in[0];
    const float* W_x    = (const float*)d_in[1];
    const float* W_h    = (const float*)d_in[2];
    const float* b_lstm = (const float*)d_in[3];
    const float* W_key  = (const float*)d_in[4];
    const float* b_key  = (const float*)d_in[5];
    const float* W_g    = (const float*)d_in[6];
    const float* b_g    = (const float*)d_in[7];
    const float* cgain  = (const float*)d_in[8];
    const float* cbias  = (const float*)d_in[9];
    float* out = (float*)d_out;

    cudaFuncSetAttribute(k_rec, cudaFuncAttributeMaxDynamicSharedMemorySize,
                         SM_FLOATS * (int)sizeof(float));

    k_init<<<128, 256>>>();
    k_pack<<<(NPACK + 255) / 256, 256>>>(W_x, W_h);
    k_gram<<<NB * 36, 256>>>(x);
    k_softmax<<<NB * NT, 128>>>(cgain, cbias);
    k_rec<<<NCTA, 256, SM_FLOATS * (int)sizeof(float)>>>(b_lstm, W_key, b_key, W_g, b_g, out);
}

// round 3
// speedup vs baseline: 1.0426x; 1.0426x over previous
#include <cuda_runtime.h>
#include <cuda_fp16.h>

#define NB   32
#define NT   512
#define ND   768
#define NK   256
#define NKP1 257
#define NH   512
#define NP   769          // NKP1 + NH
#define NCTA 128
#define NPACK (128*769*16)

// ---------------- device scratch (static; no cudaMalloc allowed) ----------
__device__ float g_S[(size_t)NB*NT*NT];    // gram -> (in place) softmax weights
__device__ float g_wc[NB*NT];              // precomputed confidence readout
__device__ float g_Wpack[NPACK];           // per-CTA packed LSTM weights
__device__ float g_hT[2*NH*NB];            // double-buffered h, layout [j][b]
__device__ float g_hB[NB*NH];              // h, layout [b][j]
__device__ float g_keyrT[NKP1*NB];         // key_r, layout [k][b]
__device__ unsigned g_arr[NCTA];           // barrier arrival flags (monotone gen)

__device__ __forceinline__ float sigmf(float x) { return 1.f / (1.f + __expf(-x)); }

// packed dual-fp32 FMA (sm_100+; ptxas never auto-fuses this)
__device__ __forceinline__ void fma2(unsigned long long &acc, unsigned long long a,
                                     unsigned long long w) {
    asm("fma.rn.f32x2 %0, %1, %2, %0;" : "+l"(acc) : "l"(a), "l"(w));
}

// flag-based grid barrier: per-CTA release store + distributed acquire poll.
// No atomic serialization; gen is monotone so flags never reset mid-run.
__device__ __forceinline__ void grid_bar(unsigned gen) {
    __syncthreads();
    if (threadIdx.x == 0)
        asm volatile("st.release.gpu.u32 [%0], %1;"
                     :: "l"(&g_arr[blockIdx.x]), "r"(gen) : "memory");
    if (threadIdx.x < NCTA) {
        unsigned v;
        do {
            asm volatile("ld.acquire.gpu.u32 %0, [%1];"
                         : "=r"(v) : "l"(&g_arr[threadIdx.x]) : "memory");
        } while (v < gen);
    }
    __syncthreads();
}

// ---------------- init: zero recurrent state + barrier flags ---------------
__global__ void k_init() {
    int i = blockIdx.x * blockDim.x + threadIdx.x;
    if (i < 2*NH*NB) g_hT[i] = 0.f;
    if (i < NKP1*NB) g_keyrT[i] = 0.f;
    if (i < NCTA) g_arr[i] = 0u;
}

// ---------------- weight pack: Wpack[ct][p][cl] ----------------------------
__global__ void k_pack(const float* __restrict__ Wx, const float* __restrict__ Wh) {
    int idx = blockIdx.x * blockDim.x + threadIdx.x;
    if (idx >= NPACK) return;
    int cl = idx & 15;
    int r  = idx >> 4;
    int p  = r % NP;
    int ct = r / NP;
    int jj = cl & 3, gate = cl >> 2;
    int col = gate * NH + ct * 4 + jj;
    float v = (p < NKP1) ? Wx[(size_t)p * 2048 + col]
                         : Wh[(size_t)(p - NKP1) * 2048 + col];
    g_Wpack[idx] = v;
}

// ---------------- gram: S[b][t][t'] = x_t . x_t'  (lower triangle) ---------
__global__ void k_gram(const float* __restrict__ x) {
    __shared__ float sa[64][17];
    __shared__ float sb[64][17];
    int bx = blockIdx.x;
    int b = bx / 36, pr = bx % 36;
    int ti = 0;
    while ((ti + 1) * (ti + 2) / 2 <= pr) ti++;
    int tj = pr - ti * (ti + 1) / 2;
    int tid = threadIdx.x;
    int ry = tid >> 4, rx = tid & 15;
    float acc[4][4] = {};
    const float* xa = x + ((size_t)b * NT + ti * 64) * ND;
    const float* xb = x + ((size_t)b * NT + tj * 64) * ND;
    for (int d0 = 0; d0 < ND; d0 += 16) {
        __syncthreads();
        for (int i = tid; i < 64 * 16; i += 256) {
            int r = i >> 4, c = i & 15;
            sa[r][c] = xa[(size_t)r * ND + d0 + c];
            sb[r][c] = xb[(size_t)r * ND + d0 + c];
        }
        __syncthreads();
#pragma unroll
        for (int dd = 0; dd < 16; ++dd) {
            float av[4], bv[4];
#pragma unroll
            for (int i = 0; i < 4; i++) av[i] = sa[ry * 4 + i][dd];
#pragma unroll
            for (int j = 0; j < 4; j++) bv[j] = sb[rx * 4 + j][dd];
#pragma unroll
            for (int i = 0; i < 4; i++)
#pragma unroll
                for (int j = 0; j < 4; j++) acc[i][j] += av[i] * bv[j];
        }
    }
#pragma unroll
    for (int i = 0; i < 4; i++) {
        int row = ti * 64 + ry * 4 + i;
        float* dst = &g_S[((size_t)b * NT + row) * NT + tj * 64 + rx * 4];
#pragma unroll
        for (int j = 0; j < 4; j++) dst[j] = acc[i][j];
    }
}

// ---------------- row softmax over t' < t, + wc ----------------------------
__global__ void k_softmax(const float* __restrict__ cgain, const float* __restrict__ cbias) {
    int bx = blockIdx.x;
    int t = bx & (NT - 1), b = bx >> 9;
    int tid = threadIdx.x;
    if (t == 0) { if (tid == 0) g_wc[b * NT] = 0.f; return; }
    float* row = &g_S[((size_t)b * NT + t) * NT];
    __shared__ float sred[4];
    __shared__ float sbuf[NT];
    float gain = cgain[0], bias = cbias[0];

    float m = -3.4e38f;
    for (int i = tid; i < t; i += 128) m = fmaxf(m, row[i]);
#pragma unroll
    for (int o = 16; o; o >>= 1) m = fmaxf(m, __shfl_xor_sync(~0u, m, o));
    if ((tid & 31) == 0) sred[tid >> 5] = m;
    __syncthreads();
    m = fmaxf(fmaxf(sred[0], sred[1]), fmaxf(sred[2], sred[3]));

    float s = 0.f;
    for (int i = tid; i < t; i += 128) { float e = __expf(row[i] - m); sbuf[i] = e; s += e; }
#pragma unroll
    for (int o = 16; o; o >>= 1) s += __shfl_xor_sync(~0u, s, o);
    __syncthreads();
    if ((tid & 31) == 0) sred[tid >> 5] = s;
    __syncthreads();
    s = sred[0] + sred[1] + sred[2] + sred[3];
    float inv = 1.f / s;

    float wca = 0.f;
    for (int i = tid; i < t; i += 128) {
        float sim = row[i];
        float w = sbuf[i] * inv;
        row[i] = w;
        wca += w * sigmf(sim * gain + bias);
    }
#pragma unroll
    for (int o = 16; o; o >>= 1) wca += __shfl_xor_sync(~0u, wca, o);
    __syncthreads();
    if ((tid & 31) == 0) sred[tid >> 5] = wca;
    __syncthreads();
    if (tid == 0) g_wc[b * NT + t] = sred[0] + sred[1] + sred[2] + sred[3];
}

// ---------------- persistent recurrence kernel -----------------------------
// smem floats: sAct[24608] | red[8736] | zbuf[528] | sMk[16384 floats = 32768 half]
// phase-2 aliases into red: sh[512] | sWrow[512] | redk[320] | sgm[1]
#define SM_SACT 24608
#define SM_RED  8736
#define SM_ZBUF 528
#define SM_SMK  16384
#define SM_FLOATS (SM_SACT + SM_RED + SM_ZBUF + SM_SMK)

__global__ void __launch_bounds__(256, 1) k_rec(
    const float* __restrict__ b_lstm, const float* __restrict__ W_key,
    const float* __restrict__ b_key,  const float* __restrict__ W_g,
    const float* __restrict__ b_g,    float* __restrict__ out)
{
    extern __shared__ float sm[];
    float* sAct  = sm;
    float* red   = sm + SM_SACT;
    float* zbuf  = red + SM_RED;
    __half* sMk  = (__half*)(zbuf + SM_ZBUF);   // [t'][64] fp16, CTA-private
    float* sh    = red;
    float* sWrow = red + 512;
    float* redk  = red + 1024;
    float* sgm   = red + 1344;

    const int ct = blockIdx.x, tid = threadIdx.x;
    const int cl = tid & 15, chunk = tid >> 4;
    const int p0 = chunk * 48;
    const int pe = (chunk == 15) ? NP : p0 + 48;
    const float* wp = g_Wpack + ((size_t)ct * NP) * 16 + cl;
    const int j0 = ct * 4;
    const int b2 = ct >> 2, kq = ct & 3, k0 = kq * 64;
    const int kl = tid & 63, qq = tid >> 6;
    float creg = 0.f;
    unsigned gen = 0;

    // ---- W_key slice register-resident for all 512 steps: wreg[i] =
    // W_key[qq*128+i][k0+kl]
    float wreg[128];
    {
        const float* wkp = W_key + (size_t)(qq * 128) * NK + k0 + kl;
#pragma unroll
        for (int i = 0; i < 128; ++i) wreg[i] = __ldg(&wkp[(size_t)i * NK]);
    }

    for (int t = 0; t < NT; ++t) {
        const int par = t & 1;
        // ---- stage activations into smem [p][b]
        {
            const float4* s1 = (const float4*)g_keyrT;
            const float4* s2 = (const float4*)(g_hT + par * (NH * NB));
            float4* d1 = (float4*)sAct;
            float4* d2 = d1 + 2056;
            for (int i = tid; i < 2056; i += 256) d1[i] = __ldcg(s1 + i);
            for (int i = tid; i < 4096; i += 256) d2[i] = __ldcg(s2 + i);
        }
        __syncthreads();
        // ---- LSTM GEMM slice, packed f32x2: 16 cols x 32 batches
        unsigned long long acc2[16];
#pragma unroll
        for (int i = 0; i < 16; i++) acc2[i] = 0ull;
#pragma unroll 2
        for (int p = p0; p < pe; ++p) {
            float w = wp[(size_t)p * 16];
            unsigned long long w2;
            asm("mov.b64 %0, {%1, %1};" : "=l"(w2) : "r"(__float_as_uint(w)));
            const ulonglong2* a4 = (const ulonglong2*)(sAct + p * 32);
#pragma unroll
            for (int q = 0; q < 8; ++q) {
                ulonglong2 aa = a4[q];
                fma2(acc2[2 * q],     aa.x, w2);
                fma2(acc2[2 * q + 1], aa.y, w2);
            }
        }
#pragma unroll
        for (int i = 0; i < 16; i++) {
            float lo, hi;
            asm("mov.b64 {%0, %1}, %2;" : "=f"(lo), "=f"(hi) : "l"(acc2[i]));
            red[(2 * i)     * 273 + cl * 17 + chunk] = lo;
            red[(2 * i + 1) * 273 + cl * 17 + chunk] = hi;
        }
        __syncthreads();
        // ---- reduce across 16 chunks + bias
        for (int o = tid; o < 512; o += 256) {
            int c = o >> 5, b = o & 31;
            const float* rr = &red[b * 273 + c * 17];
            float s = 0.f;
#pragma unroll
            for (int ch = 0; ch < 16; ++ch) s += rr[ch];
            int gate = c >> 2, jj = c & 3;
            s += __ldg(&b_lstm[gate * NH + j0 + jj]);
            zbuf[c * 33 + b] = s;
        }
        __syncthreads();
        // ---- gate math; c-state register-resident in owner thread
        if (tid < 128) {
            int jj = tid >> 5, b = tid & 31;
            float zi = zbuf[(0 + jj) * 33 + b];
            float zf = zbuf[(4 + jj) * 33 + b];
            float zc = zbuf[(8 + jj) * 33 + b];
            float zo = zbuf[(12 + jj) * 33 + b];
            float ig = sigmf(zi), fg = sigmf(zf);
            float gc = tanhf(zc), og = sigmf(zo);
            creg = fg * creg + ig * gc;
            float hv = og * tanhf(creg);
            int j = j0 + jj;
            __stcg(&g_hT[(par ^ 1) * (NH * NB) + j * NB + b], hv);
            __stcg(&g_hB[b * NH + j], hv);
            if (t == NT - 1) out[b * NH + j] = hv;
        }
        if (t == NT - 1) break;
        grid_bar(++gen);

        // ================= phase 2: CTA = (b2, k-quarter) ==================
        {
            const float4* src = (const float4*)(g_hB + b2 * NH);
            float4* dst = (float4*)sh;
            if (tid < 128) dst[tid] = __ldcg(src + tid);
        }
        for (int i = tid; i < t; i += 256)
            sWrow[i] = __ldcg(&g_S[((size_t)b2 * NT + t) * NT + i]);
        __syncthreads();
        // gate scalar g = sigmoid(h . W_g + b_g)
        float pg = sh[tid] * __ldg(&W_g[tid]) + sh[tid + 256] * __ldg(&W_g[tid + 256]);
#pragma unroll
        for (int o = 16; o; o >>= 1) pg += __shfl_xor_sync(~0u, pg, o);
        if ((tid & 31) == 0) redk[tid >> 5] = pg;
        __syncthreads();
        if (tid == 0) {
            float s = 0.f;
            for (int i = 0; i < 8; i++) s += redk[i];
            sgm[0] = sigmf(s + __ldg(&b_g[0]));
        }
        __syncthreads();
        float gv = sgm[0];
        // key_w = h . W_key from register-resident slice (64 cols, 4-way split)
        float kacc = 0.f;
        {
            const float* shq = sh + qq * 128;
#pragma unroll
            for (int i = 0; i < 128; ++i) kacc += shq[i] * wreg[i];
        }
        __syncthreads();
        redk[kl * 5 + qq] = kacc;
        __syncthreads();
        if (tid < 64) {
            float kw = redk[tid * 5] + redk[tid * 5 + 1] + redk[tid * 5 + 2] + redk[tid * 5 + 3]
                     + __ldg(&b_key[k0 + tid]);
            sMk[t * 64 + tid] = __float2half_rn(kw);
        }
        // attention readout from fp16 smem Mk (CTA-private)
        float aacc = 0.f;
        if (t > 0) {
            const __half* mkp = sMk + kl;
#pragma unroll 8
            for (int t2 = qq; t2 < t; t2 += 4)
                aacc += sWrow[t2] * __half2float(mkp[t2 * 64]);
        }
        __syncthreads();
        redk[kl * 5 + qq] = aacc;
        __syncthreads();
        if (tid < 64) {
            float kr = (t > 0)
                ? gv * (redk[tid * 5] + redk[tid * 5 + 1] + redk[tid * 5 + 2] + redk[tid * 5 + 3])
                : 0.f;
            __stcg(&g_keyrT[(k0 + tid) * NB + b2], kr);
        }
        if (tid == 64 && kq == 0) {
            float kr = (t > 0) ? gv * __ldg(&g_wc[b2 * NT + t]) : 0.f;
            __stcg(&g_keyrT[NK * NB + b2], kr);
        }
        grid_bar(++gen);
    }
}

// ---------------- launch ---------------------------------------------------
extern "C" void kernel_launch(void* const* d_in, const int* in_sizes, int n_in,
                              void* d_out, int out_size) {
    const float* x      = (const float*)d_in[0];
    const float* W_x    = (const float*)d_in[1];
    const float* W_h    = (const float*)d_in[2];
    const float* b_lstm = (const float*)d_in[3];
    const float* W_key  = (const float*)d_in[4];
    const float* b_key  = (const float*)d_in[5];
    const float* W_g    = (const float*)d_in[6];
    const float* b_g    = (const float*)d_in[7];
    const float* cgain  = (const float*)d_in[8];
    const float* cbias  = (const float*)d_in[9];
    float* out = (float*)d_out;

    cudaFuncSetAttribute(k_rec, cudaFuncAttributeMaxDynamicSharedMemorySize,
                         SM_FLOATS * (int)sizeof(float));

    k_init<<<128, 256>>>();
    k_pack<<<(NPACK + 255) / 256, 256>>>(W_x, W_h);
    k_gram<<<NB * 36, 256>>>(x);
    k_softmax<<<NB * NT, 128>>>(cgain, cbias);
    k_rec<<<NCTA, 256, SM_FLOATS * (int)sizeof(float)>>>(b_lstm, W_key, b_key, W_g, b_g, out);
}

// round 4
// speedup vs baseline: 1.2237x; 1.1737x over previous
#include <cuda_runtime.h>
#include <cuda_fp16.h>

#define NB   32
#define NT   512
#define ND   768
#define NK   256
#define NKP1 257
#define NH   512
#define NP   769          // NKP1 + NH
#define NCTA 128
#define NPACK (128*769*16)

// ---------------- device scratch (static; no cudaMalloc allowed) ----------
__device__ float g_S[(size_t)NB*NT*NT];    // gram -> (in place) softmax weights
__device__ float g_wc[NB*NT];              // precomputed confidence readout
__device__ float g_Wpack[NPACK];           // per-CTA packed LSTM weights
__device__ float g_hT[2*NH*NB];            // double-buffered h, layout [j][b]
__device__ float g_hB[NB*NH];              // h, layout [b][j]
__device__ float g_keyrT[NKP1*NB];         // key_r, layout [k][b]
__device__ unsigned g_arr[NCTA];           // barrier arrival flags (monotone gen)

__device__ __forceinline__ float sigmf(float x) { return 1.f / (1.f + __expf(-x)); }

// packed dual-fp32 FMA (sm_100+; ptxas never auto-fuses this)
__device__ __forceinline__ void fma2(unsigned long long &acc, unsigned long long a,
                                     unsigned long long w) {
    asm("fma.rn.f32x2 %0, %1, %2, %0;" : "+l"(acc) : "l"(a), "l"(w));
}

// flag-based grid barrier: per-CTA release store + distributed acquire poll.
__device__ __forceinline__ void grid_bar(unsigned gen) {
    __syncthreads();
    if (threadIdx.x == 0)
        asm volatile("st.release.gpu.u32 [%0], %1;"
                     :: "l"(&g_arr[blockIdx.x]), "r"(gen) : "memory");
    if (threadIdx.x < NCTA) {
        unsigned v;
        do {
            asm volatile("ld.acquire.gpu.u32 %0, [%1];"
                         : "=r"(v) : "l"(&g_arr[threadIdx.x]) : "memory");
        } while (v < gen);
    }
    __syncthreads();
}

// ---------------- init: zero recurrent state + barrier flags ---------------
__global__ void k_init() {
    int i = blockIdx.x * blockDim.x + threadIdx.x;
    if (i < 2*NH*NB) g_hT[i] = 0.f;
    if (i < NKP1*NB) g_keyrT[i] = 0.f;
    if (i < NCTA) g_arr[i] = 0u;
}

// ---------------- weight pack: Wpack[ct][p][cl] ----------------------------
__global__ void k_pack(const float* __restrict__ Wx, const float* __restrict__ Wh) {
    int idx = blockIdx.x * blockDim.x + threadIdx.x;
    if (idx >= NPACK) return;
    int cl = idx & 15;
    int r  = idx >> 4;
    int p  = r % NP;
    int ct = r / NP;
    int jj = cl & 3, gate = cl >> 2;
    int col = gate * NH + ct * 4 + jj;
    float v = (p < NKP1) ? Wx[(size_t)p * 2048 + col]
                         : Wh[(size_t)(p - NKP1) * 2048 + col];
    g_Wpack[idx] = v;
}

// ---------------- gram: S[b][t][t'] = x_t . x_t'  (lower triangle) ---------
__global__ void k_gram(const float* __restrict__ x) {
    __shared__ float sa[64][17];
    __shared__ float sb[64][17];
    int bx = blockIdx.x;
    int b = bx / 36, pr = bx % 36;
    int ti = 0;
    while ((ti + 1) * (ti + 2) / 2 <= pr) ti++;
    int tj = pr - ti * (ti + 1) / 2;
    int tid = threadIdx.x;
    int ry = tid >> 4, rx = tid & 15;
    float acc[4][4] = {};
    const float* xa = x + ((size_t)b * NT + ti * 64) * ND;
    const float* xb = x + ((size_t)b * NT + tj * 64) * ND;
    for (int d0 = 0; d0 < ND; d0 += 16) {
        __syncthreads();
        for (int i = tid; i < 64 * 16; i += 256) {
            int r = i >> 4, c = i & 15;
            sa[r][c] = xa[(size_t)r * ND + d0 + c];
            sb[r][c] = xb[(size_t)r * ND + d0 + c];
        }
        __syncthreads();
#pragma unroll
        for (int dd = 0; dd < 16; ++dd) {
            float av[4], bv[4];
#pragma unroll
            for (int i = 0; i < 4; i++) av[i] = sa[ry * 4 + i][dd];
#pragma unroll
            for (int j = 0; j < 4; j++) bv[j] = sb[rx * 4 + j][dd];
#pragma unroll
            for (int i = 0; i < 4; i++)
#pragma unroll
                for (int j = 0; j < 4; j++) acc[i][j] += av[i] * bv[j];
        }
    }
#pragma unroll
    for (int i = 0; i < 4; i++) {
        int row = ti * 64 + ry * 4 + i;
        float* dst = &g_S[((size_t)b * NT + row) * NT + tj * 64 + rx * 4];
#pragma unroll
        for (int j = 0; j < 4; j++) dst[j] = acc[i][j];
    }
}

// ---------------- row softmax over t' < t, + wc ----------------------------
__global__ void k_softmax(const float* __restrict__ cgain, const float* __restrict__ cbias) {
    int bx = blockIdx.x;
    int t = bx & (NT - 1), b = bx >> 9;
    int tid = threadIdx.x;
    if (t == 0) { if (tid == 0) g_wc[b * NT] = 0.f; return; }
    float* row = &g_S[((size_t)b * NT + t) * NT];
    __shared__ float sred[4];
    __shared__ float sbuf[NT];
    float gain = cgain[0], bias = cbias[0];

    float m = -3.4e38f;
    for (int i = tid; i < t; i += 128) m = fmaxf(m, row[i]);
#pragma unroll
    for (int o = 16; o; o >>= 1) m = fmaxf(m, __shfl_xor_sync(~0u, m, o));
    if ((tid & 31) == 0) sred[tid >> 5] = m;
    __syncthreads();
    m = fmaxf(fmaxf(sred[0], sred[1]), fmaxf(sred[2], sred[3]));

    float s = 0.f;
    for (int i = tid; i < t; i += 128) { float e = __expf(row[i] - m); sbuf[i] = e; s += e; }
#pragma unroll
    for (int o = 16; o; o >>= 1) s += __shfl_xor_sync(~0u, s, o);
    __syncthreads();
    if ((tid & 31) == 0) sred[tid >> 5] = s;
    __syncthreads();
    s = sred[0] + sred[1] + sred[2] + sred[3];
    float inv = 1.f / s;

    float wca = 0.f;
    for (int i = tid; i < t; i += 128) {
        float sim = row[i];
        float w = sbuf[i] * inv;
        row[i] = w;
        wca += w * sigmf(sim * gain + bias);
    }
#pragma unroll
    for (int o = 16; o; o >>= 1) wca += __shfl_xor_sync(~0u, wca, o);
    __syncthreads();
    if ((tid & 31) == 0) sred[tid >> 5] = wca;
    __syncthreads();
    if (tid == 0) g_wc[b * NT + t] = sred[0] + sred[1] + sred[2] + sred[3];
}

// ---------------- persistent recurrence kernel -----------------------------
// smem floats: sAct[24608] | red[8736] | zbuf[528] | sMk[16384 floats = 32768 half]
// phase-2 aliases into red: sh[512] | sWrow[512] | redk[320] | sgm[1]
#define SM_SACT 24608
#define SM_RED  8736
#define SM_ZBUF 528
#define SM_SMK  16384
#define SM_FLOATS (SM_SACT + SM_RED + SM_ZBUF + SM_SMK)

__global__ void __launch_bounds__(256, 1) k_rec(
    const float* __restrict__ b_lstm, const float* __restrict__ W_key,
    const float* __restrict__ b_key,  const float* __restrict__ W_g,
    const float* __restrict__ b_g,    float* __restrict__ out)
{
    extern __shared__ float sm[];
    float* sAct  = sm;
    float* red   = sm + SM_SACT;
    float* zbuf  = red + SM_RED;
    __half* sMk  = (__half*)(zbuf + SM_ZBUF);   // [t'][64] fp16, CTA-private
    float* sh    = red;
    float* sWrow = red + 512;
    float* redk  = red + 1024;
    float* sgm   = red + 1344;

    const int ct = blockIdx.x, tid = threadIdx.x;
    const int cl = tid & 15, chunk = tid >> 4;
    const int p0 = chunk * 48;
    const int qrot = (chunk & 1) << 2;          // bank-conflict breaker
    const float* wp = g_Wpack + ((size_t)ct * NP) * 16 + cl;
    const int j0 = ct * 4;
    const int b2 = ct >> 2, kq = ct & 3, k0 = kq * 64;
    const int kl = tid & 63, qq = tid >> 6;
    float creg = 0.f;
    unsigned gen = 0;

    // ---- LSTM weight slice register-resident for all 512 steps
    float wlstm[48];
#pragma unroll
    for (int i = 0; i < 48; ++i) wlstm[i] = __ldg(&wp[(size_t)(p0 + i) * 16]);
    const float wextra = (chunk == 15) ? __ldg(&wp[(size_t)768 * 16]) : 0.f;

    // ---- W_key slice as 64 half2 registers: pair i covers rows qq*128+2i,+1
    unsigned wk2[64];
    {
        const float* wkp = W_key + (size_t)(qq * 128) * NK + k0 + kl;
#pragma unroll
        for (int i = 0; i < 64; ++i) {
            float w0 = __ldg(&wkp[(size_t)(2 * i) * NK]);
            float w1 = __ldg(&wkp[(size_t)(2 * i + 1) * NK]);
            __half2 h2 = __floats2half2_rn(w0, w1);
            wk2[i] = *(unsigned*)&h2;
        }
    }

    for (int t = 0; t < NT; ++t) {
        const int par = t & 1;
        // ---- stage activations into smem [p][b]
        {
            const float4* s1 = (const float4*)g_keyrT;
            const float4* s2 = (const float4*)(g_hT + par * (NH * NB));
            float4* d1 = (float4*)sAct;
            float4* d2 = d1 + 2056;
            for (int i = tid; i < 2056; i += 256) d1[i] = __ldcg(s1 + i);
            for (int i = tid; i < 4096; i += 256) d2[i] = __ldcg(s2 + i);
        }
        __syncthreads();
        // ---- LSTM GEMM slice: weights in registers, activations in smem
        unsigned long long acc2[16];
#pragma unroll
        for (int i = 0; i < 16; i++) acc2[i] = 0ull;
#pragma unroll
        for (int i = 0; i < 48; ++i) {
            unsigned long long w2;
            asm("mov.b64 %0, {%1, %1};" : "=l"(w2) : "r"(__float_as_uint(wlstm[i])));
            const ulonglong2* a4 = (const ulonglong2*)(sAct + (p0 + i) * 32);
#pragma unroll
            for (int q = 0; q < 8; ++q) {
                ulonglong2 aa = a4[(q + qrot) & 7];
                fma2(acc2[2 * q],     aa.x, w2);
                fma2(acc2[2 * q + 1], aa.y, w2);
            }
        }
        { // p = 768 handled by all threads, weight 0 except chunk 15
            unsigned long long w2;
            asm("mov.b64 %0, {%1, %1};" : "=l"(w2) : "r"(__float_as_uint(wextra)));
            const ulonglong2* a4 = (const ulonglong2*)(sAct + 768 * 32);
#pragma unroll
            for (int q = 0; q < 8; ++q) {
                ulonglong2 aa = a4[(q + qrot) & 7];
                fma2(acc2[2 * q],     aa.x, w2);
                fma2(acc2[2 * q + 1], aa.y, w2);
            }
        }
#pragma unroll
        for (int q = 0; q < 8; ++q) {
            int bb = ((q + qrot) & 7) * 4;       // batch group this acc pair holds
            float f0, f1, f2, f3;
            asm("mov.b64 {%0, %1}, %2;" : "=f"(f0), "=f"(f1) : "l"(acc2[2 * q]));
            asm("mov.b64 {%0, %1}, %2;" : "=f"(f2), "=f"(f3) : "l"(acc2[2 * q + 1]));
            red[(bb + 0) * 273 + cl * 17 + chunk] = f0;
            red[(bb + 1) * 273 + cl * 17 + chunk] = f1;
            red[(bb + 2) * 273 + cl * 17 + chunk] = f2;
            red[(bb + 3) * 273 + cl * 17 + chunk] = f3;
        }
        __syncthreads();
        // ---- reduce across 16 chunks + bias
        for (int o = tid; o < 512; o += 256) {
            int c = o >> 5, b = o & 31;
            const float* rr = &red[b * 273 + c * 17];
            float s = 0.f;
#pragma unroll
            for (int ch = 0; ch < 16; ++ch) s += rr[ch];
            int gate = c >> 2, jj = c & 3;
            s += __ldg(&b_lstm[gate * NH + j0 + jj]);
            zbuf[c * 33 + b] = s;
        }
        __syncthreads();
        // ---- gate math; c-state register-resident in owner thread
        if (tid < 128) {
            int jj = tid >> 5, b = tid & 31;
            float zi = zbuf[(0 + jj) * 33 + b];
            float zf = zbuf[(4 + jj) * 33 + b];
            float zc = zbuf[(8 + jj) * 33 + b];
            float zo = zbuf[(12 + jj) * 33 + b];
            float ig = sigmf(zi), fg = sigmf(zf);
            float gc = tanhf(zc), og = sigmf(zo);
            creg = fg * creg + ig * gc;
            float hv = og * tanhf(creg);
            int j = j0 + jj;
            __stcg(&g_hT[(par ^ 1) * (NH * NB) + j * NB + b], hv);
            __stcg(&g_hB[b * NH + j], hv);
            if (t == NT - 1) out[b * NH + j] = hv;
        }
        if (t == NT - 1) break;
        grid_bar(++gen);

        // ================= phase 2: CTA = (b2, k-quarter) ==================
        {
            const float4* src = (const float4*)(g_hB + b2 * NH);
            float4* dst = (float4*)sh;
            if (tid < 128) dst[tid] = __ldcg(src + tid);
        }
        for (int i = tid; i < t; i += 256)
            sWrow[i] = __ldcg(&g_S[((size_t)b2 * NT + t) * NT + i]);
        __syncthreads();
        // gate scalar g = sigmoid(h . W_g + b_g)
        float pg = sh[tid] * __ldg(&W_g[tid]) + sh[tid + 256] * __ldg(&W_g[tid + 256]);
#pragma unroll
        for (int o = 16; o; o >>= 1) pg += __shfl_xor_sync(~0u, pg, o);
        if ((tid & 31) == 0) redk[tid >> 5] = pg;
        __syncthreads();
        if (tid == 0) {
            float s = 0.f;
            for (int i = 0; i < 8; i++) s += redk[i];
            sgm[0] = sigmf(s + __ldg(&b_g[0]));
        }
        __syncthreads();
        float gv = sgm[0];
        // key_w = h . W_key from register-resident half2 slice (4 chains)
        float ka[4] = {0.f, 0.f, 0.f, 0.f};
        {
            const float* shq = sh + qq * 128;
#pragma unroll
            for (int i = 0; i < 64; ++i) {
                __half2 hw = *(__half2*)&wk2[i];
                float2 wf = __half22float2(hw);
                ka[2 * (i & 1)]     += shq[2 * i]     * wf.x;
                ka[2 * (i & 1) + 1] += shq[2 * i + 1] * wf.y;
            }
        }
        float kacc = (ka[0] + ka[1]) + (ka[2] + ka[3]);
        __syncthreads();
        redk[kl * 5 + qq] = kacc;
        __syncthreads();
        if (tid < 64) {
            float kw = redk[tid * 5] + redk[tid * 5 + 1] + redk[tid * 5 + 2] + redk[tid * 5 + 3]
                     + __ldg(&b_key[k0 + tid]);
            sMk[t * 64 + tid] = __float2half_rn(kw);
        }
        // attention readout from fp16 smem Mk (4 chains)
        float aacc;
        {
            float a0 = 0.f, a1 = 0.f, a2 = 0.f, a3 = 0.f;
            const __half* mkp = sMk + kl;
            int t2 = qq;
            for (; t2 + 12 < t; t2 += 16) {
                a0 += sWrow[t2]      * __half2float(mkp[t2 * 64]);
                a1 += sWrow[t2 + 4]  * __half2float(mkp[(t2 + 4) * 64]);
                a2 += sWrow[t2 + 8]  * __half2float(mkp[(t2 + 8) * 64]);
                a3 += sWrow[t2 + 12] * __half2float(mkp[(t2 + 12) * 64]);
            }
            for (; t2 < t; t2 += 4)
                a0 += sWrow[t2] * __half2float(mkp[t2 * 64]);
            aacc = (a0 + a1) + (a2 + a3);
        }
        __syncthreads();
        redk[kl * 5 + qq] = aacc;
        __syncthreads();
        if (tid < 64) {
            float kr = (t > 0)
                ? gv * (redk[tid * 5] + redk[tid * 5 + 1] + redk[tid * 5 + 2] + redk[tid * 5 + 3])
                : 0.f;
            __stcg(&g_keyrT[(k0 + tid) * NB + b2], kr);
        }
        if (tid == 64 && kq == 0) {
            float kr = (t > 0) ? gv * __ldg(&g_wc[b2 * NT + t]) : 0.f;
            __stcg(&g_keyrT[NK * NB + b2], kr);
        }
        grid_bar(++gen);
    }
}

// ---------------- launch ---------------------------------------------------
extern "C" void kernel_launch(void* const* d_in, const int* in_sizes, int n_in,
                              void* d_out, int out_size) {
    const float* x      = (const float*)d_in[0];
    const float* W_x    = (const float*)d_in[1];
    const float* W_h    = (const float*)d_in[2];
    const float* b_lstm = (const float*)d_in[3];
    const float* W_key  = (const float*)d_in[4];
    const float* b_key  = (const float*)d_in[5];
    const float* W_g    = (const float*)d_in[6];
    const float* b_g    = (const float*)d_in[7];
    const float* cgain  = (const float*)d_in[8];
    const float* cbias  = (const float*)d_in[9];
    float* out = (float*)d_out;

    cudaFuncSetAttribute(k_rec, cudaFuncAttributeMaxDynamicSharedMemorySize,
                         SM_FLOATS * (int)sizeof(float));

    k_init<<<128, 256>>>();
    k_pack<<<(NPACK + 255) / 256, 256>>>(W_x, W_h);
    k_gram<<<NB * 36, 256>>>(x);
    k_softmax<<<NB * NT, 128>>>(cgain, cbias);
    k_rec<<<NCTA, 256, SM_FLOATS * (int)sizeof(float)>>>(b_lstm, W_key, b_key, W_g, b_g, out);
}

// round 5
// speedup vs baseline: 1.9180x; 1.5674x over previous
#include <cuda_runtime.h>
#include <cuda_fp16.h>

#define NB   32
#define NT   512
#define ND   768
#define NK   256
#define NKP1 257
#define NH   512
#define NP   769          // NKP1 + NH
#define NCTA 128
#define NPACK (128*769*16)

// ---------------- device scratch (static; no cudaMalloc allowed) ----------
__device__ float g_S[(size_t)NB*NT*NT];    // gram -> (in place) softmax weights
__device__ float g_wc[NB*NT];              // precomputed confidence readout
__device__ float g_Wpack[NPACK];           // per-CTA packed LSTM weights
__device__ float g_hT[2*NH*NB];            // double-buffered h, layout [j][b]
__device__ float g_hB[NB*NH];              // h, layout [b][j]
__device__ float g_keyrT[NKP1*NB];         // key_r, layout [k][b]
__device__ unsigned g_arr[NCTA*32];        // barrier flags, one 128B line each

__device__ __forceinline__ float sigmf(float x) { return 1.f / (1.f + __expf(-x)); }

// packed dual-fp32 FMA (sm_100+; ptxas never auto-fuses this)
__device__ __forceinline__ void fma2(unsigned long long &acc, unsigned long long a,
                                     unsigned long long w) {
    asm("fma.rn.f32x2 %0, %1, %2, %0;" : "+l"(acc) : "l"(a), "l"(w));
}

__device__ __forceinline__ void cp_async16(void* smem_dst, const void* gsrc) {
    unsigned s = (unsigned)__cvta_generic_to_shared(smem_dst);
    asm volatile("cp.async.cg.shared.global [%0], [%1], 16;" :: "r"(s), "l"(gsrc));
}

// flag-based grid barrier; each flag on its own 128-B line (no L2 sector storms)
__device__ __forceinline__ void grid_bar(unsigned gen) {
    __syncthreads();
    if (threadIdx.x == 0)
        asm volatile("st.release.gpu.u32 [%0], %1;"
                     :: "l"(&g_arr[blockIdx.x * 32]), "r"(gen) : "memory");
    if (threadIdx.x < NCTA) {
        unsigned v;
        do {
            asm volatile("ld.acquire.gpu.u32 %0, [%1];"
                         : "=r"(v) : "l"(&g_arr[threadIdx.x * 32]) : "memory");
        } while (v < gen);
    }
    __syncthreads();
}

// ---------------- weight pack + state/flag init ----------------------------
__global__ void k_pack(const float* __restrict__ Wx, const float* __restrict__ Wh) {
    int idx = blockIdx.x * blockDim.x + threadIdx.x;
    if (idx < 2*NH*NB) g_hT[idx] = 0.f;
    if (idx < NKP1*NB) g_keyrT[idx] = 0.f;
    if (idx < NCTA*32) g_arr[idx] = 0u;
    if (idx >= NPACK) return;
    int cl = idx & 15;
    int r  = idx >> 4;
    int p  = r % NP;
    int ct = r / NP;
    int jj = cl & 3, gate = cl >> 2;
    int col = gate * NH + ct * 4 + jj;
    float v = (p < NKP1) ? Wx[(size_t)p * 2048 + col]
                         : Wh[(size_t)(p - NKP1) * 2048 + col];
    g_Wpack[idx] = v;
}

// ---------------- gram: S[b][t][t'] = x_t . x_t'  (lower triangle) ---------
__global__ void k_gram(const float* __restrict__ x) {
    __shared__ float sa[64][17];
    __shared__ float sb[64][17];
    int bx = blockIdx.x;
    int b = bx / 36, pr = bx % 36;
    int ti = 0;
    while ((ti + 1) * (ti + 2) / 2 <= pr) ti++;
    int tj = pr - ti * (ti + 1) / 2;
    int tid = threadIdx.x;
    int ry = tid >> 4, rx = tid & 15;
    float acc[4][4] = {};
    const float* xa = x + ((size_t)b * NT + ti * 64) * ND;
    const float* xb = x + ((size_t)b * NT + tj * 64) * ND;
    for (int d0 = 0; d0 < ND; d0 += 16) {
        __syncthreads();
        for (int i = tid; i < 64 * 16; i += 256) {
            int r = i >> 4, c = i & 15;
            sa[r][c] = xa[(size_t)r * ND + d0 + c];
            sb[r][c] = xb[(size_t)r * ND + d0 + c];
        }
        __syncthreads();
#pragma unroll
        for (int dd = 0; dd < 16; ++dd) {
            float av[4], bv[4];
#pragma unroll
            for (int i = 0; i < 4; i++) av[i] = sa[ry * 4 + i][dd];
#pragma unroll
            for (int j = 0; j < 4; j++) bv[j] = sb[rx * 4 + j][dd];
#pragma unroll
            for (int i = 0; i < 4; i++)
#pragma unroll
                for (int j = 0; j < 4; j++) acc[i][j] += av[i] * bv[j];
        }
    }
#pragma unroll
    for (int i = 0; i < 4; i++) {
        int row = ti * 64 + ry * 4 + i;
        float* dst = &g_S[((size_t)b * NT + row) * NT + tj * 64 + rx * 4];
#pragma unroll
        for (int j = 0; j < 4; j++) dst[j] = acc[i][j];
    }
}

// ---------------- row softmax over t' < t, + wc ----------------------------
__global__ void k_softmax(const float* __restrict__ cgain, const float* __restrict__ cbias) {
    int bx = blockIdx.x;
    int t = bx & (NT - 1), b = bx >> 9;
    int tid = threadIdx.x;
    if (t == 0) { if (tid == 0) g_wc[b * NT] = 0.f; return; }
    float* row = &g_S[((size_t)b * NT + t) * NT];
    __shared__ float sred[4];
    __shared__ float sbuf[NT];
    float gain = cgain[0], bias = cbias[0];

    float m = -3.4e38f;
    for (int i = tid; i < t; i += 128) m = fmaxf(m, row[i]);
#pragma unroll
    for (int o = 16; o; o >>= 1) m = fmaxf(m, __shfl_xor_sync(~0u, m, o));
    if ((tid & 31) == 0) sred[tid >> 5] = m;
    __syncthreads();
    m = fmaxf(fmaxf(sred[0], sred[1]), fmaxf(sred[2], sred[3]));

    float s = 0.f;
    for (int i = tid; i < t; i += 128) { float e = __expf(row[i] - m); sbuf[i] = e; s += e; }
#pragma unroll
    for (int o = 16; o; o >>= 1) s += __shfl_xor_sync(~0u, s, o);
    __syncthreads();
    if ((tid & 31) == 0) sred[tid >> 5] = s;
    __syncthreads();
    s = sred[0] + sred[1] + sred[2] + sred[3];
    float inv = 1.f / s;

    float wca = 0.f;
    for (int i = tid; i < t; i += 128) {
        float sim = row[i];
        float w = sbuf[i] * inv;
        row[i] = w;
        wca += w * sigmf(sim * gain + bias);
    }
#pragma unroll
    for (int o = 16; o; o >>= 1) wca += __shfl_xor_sync(~0u, wca, o);
    __syncthreads();
    if ((tid & 31) == 0) sred[tid >> 5] = wca;
    __syncthreads();
    if (tid == 0) g_wc[b * NT + t] = sred[0] + sred[1] + sred[2] + sred[3];
}

// ---------------- persistent recurrence kernel -----------------------------
// smem floats: sAct[24608] | red[8736] | zbuf[528] | sMk[16384 floats = 32768 half]
// phase-2 aliases into red: sh[512] | sWrow[512] | redk[320] | sgm[1]
#define SM_SACT 24608
#define SM_RED  8736
#define SM_ZBUF 528
#define SM_SMK  16384
#define SM_FLOATS (SM_SACT + SM_RED + SM_ZBUF + SM_SMK)

__global__ void __launch_bounds__(256, 1) k_rec(
    const float* __restrict__ b_lstm, const float* __restrict__ W_key,
    const float* __restrict__ b_key,  const float* __restrict__ W_g,
    const float* __restrict__ b_g,    float* __restrict__ out)
{
    extern __shared__ float sm[];
    float* sAct  = sm;
    float* red   = sm + SM_SACT;
    float* zbuf  = red + SM_RED;
    __half* sMk  = (__half*)(zbuf + SM_ZBUF);   // [t'][64] fp16, CTA-private
    float* sh    = red;
    float* sWrow = red + 512;
    float* redk  = red + 1024;
    float* sgm   = red + 1344;

    const int ct = blockIdx.x, tid = threadIdx.x;
    const int cl = tid & 15, chunk = tid >> 4;
    const int p0 = chunk * 48;
    const int qrot = (chunk & 1) << 2;          // bank-conflict breaker
    const float* wp = g_Wpack + ((size_t)ct * NP) * 16 + cl;
    const int j0 = ct * 4;
    const int b2 = ct >> 2, kq = ct & 3, k0 = kq * 64;
    const int kl = tid & 63, qq = tid >> 6;
    float creg = 0.f;
    unsigned gen = 0;

    // ---- LSTM weight slice register-resident for all 512 steps
    float wlstm[48];
#pragma unroll
    for (int i = 0; i < 48; ++i) wlstm[i] = __ldg(&wp[(size_t)(p0 + i) * 16]);
    const float wextra = (chunk == 15) ? __ldg(&wp[(size_t)768 * 16]) : 0.f;

    // ---- W_key slice as 64 half2 registers: pair i covers rows qq*128+2i,+1
    unsigned wk2[64];
    {
        const float* wkp = W_key + (size_t)(qq * 128) * NK + k0 + kl;
#pragma unroll
        for (int i = 0; i < 64; ++i) {
            float w0 = __ldg(&wkp[(size_t)(2 * i) * NK]);
            float w1 = __ldg(&wkp[(size_t)(2 * i + 1) * NK]);
            __half2 h2 = __floats2half2_rn(w0, w1);
            wk2[i] = *(unsigned*)&h2;
        }
    }

    for (int t = 0; t < NT; ++t) {
        const int par = t & 1;
        // ---- stage key_r into smem; h arrives via cp.async prefetch (t>0)
        {
            const float4* s1 = (const float4*)g_keyrT;
            float4* d1 = (float4*)sAct;
            for (int i = tid; i < 2056; i += 256) d1[i] = __ldcg(s1 + i);
            if (t == 0) {
                const float4* s2 = (const float4*)(g_hT + par * (NH * NB));
                float4* d2 = d1 + 2056;
                for (int i = tid; i < 4096; i += 256) d2[i] = __ldcg(s2 + i);
            } else {
                asm volatile("cp.async.wait_all;" ::: "memory");
            }
        }
        __syncthreads();
        // ---- LSTM GEMM slice: weights in registers, activations in smem
        unsigned long long acc2[16];
#pragma unroll
        for (int i = 0; i < 16; i++) acc2[i] = 0ull;
#pragma unroll
        for (int i = 0; i < 48; ++i) {
            unsigned long long w2;
            asm("mov.b64 %0, {%1, %1};" : "=l"(w2) : "r"(__float_as_uint(wlstm[i])));
            const ulonglong2* a4 = (const ulonglong2*)(sAct + (p0 + i) * 32);
#pragma unroll
            for (int q = 0; q < 8; ++q) {
                ulonglong2 aa = a4[(q + qrot) & 7];
                fma2(acc2[2 * q],     aa.x, w2);
                fma2(acc2[2 * q + 1], aa.y, w2);
            }
        }
        if (chunk == 15) { // p = 768 tail, warp 7 only
            unsigned long long w2;
            asm("mov.b64 %0, {%1, %1};" : "=l"(w2) : "r"(__float_as_uint(wextra)));
            const ulonglong2* a4 = (const ulonglong2*)(sAct + 768 * 32);
#pragma unroll
            for (int q = 0; q < 8; ++q) {
                ulonglong2 aa = a4[(q + qrot) & 7];
                fma2(acc2[2 * q],     aa.x, w2);
                fma2(acc2[2 * q + 1], aa.y, w2);
            }
        }
#pragma unroll
        for (int q = 0; q < 8; ++q) {
            int bb = ((q + qrot) & 7) * 4;       // batch group this acc pair holds
            float f0, f1, f2, f3;
            asm("mov.b64 {%0, %1}, %2;" : "=f"(f0), "=f"(f1) : "l"(acc2[2 * q]));
            asm("mov.b64 {%0, %1}, %2;" : "=f"(f2), "=f"(f3) : "l"(acc2[2 * q + 1]));
            red[(bb + 0) * 273 + cl * 17 + chunk] = f0;
            red[(bb + 1) * 273 + cl * 17 + chunk] = f1;
            red[(bb + 2) * 273 + cl * 17 + chunk] = f2;
            red[(bb + 3) * 273 + cl * 17 + chunk] = f3;
        }
        __syncthreads();
        // ---- reduce across 16 chunks + bias
        for (int o = tid; o < 512; o += 256) {
            int c = o >> 5, b = o & 31;
            const float* rr = &red[b * 273 + c * 17];
            float s = 0.f;
#pragma unroll
            for (int ch = 0; ch < 16; ++ch) s += rr[ch];
            int gate = c >> 2, jj = c & 3;
            s += __ldg(&b_lstm[gate * NH + j0 + jj]);
            zbuf[c * 33 + b] = s;
        }
        __syncthreads();
        // ---- gate math; c-state register-resident in owner thread
        if (tid < 128) {
            int jj = tid >> 5, b = tid & 31;
            float zi = zbuf[(0 + jj) * 33 + b];
            float zf = zbuf[(4 + jj) * 33 + b];
            float zc = zbuf[(8 + jj) * 33 + b];
            float zo = zbuf[(12 + jj) * 33 + b];
            float ig = sigmf(zi), fg = sigmf(zf);
            float gc = tanhf(zc), og = sigmf(zo);
            creg = fg * creg + ig * gc;
            float hv = og * tanhf(creg);
            int j = j0 + jj;
            __stcg(&g_hT[(par ^ 1) * (NH * NB) + j * NB + b], hv);
            __stcg(&g_hB[b * NH + j], hv);
            if (t == NT - 1) out[b * NH + j] = hv;
        }
        if (t == NT - 1) break;
        grid_bar(++gen);

        // ================= phase 2: CTA = (b2, k-quarter) ==================
        // prefetch next step's h (g_hT[par^1], visible after bar #1) into sAct
        {
            const float4* s2 = (const float4*)(g_hT + (par ^ 1) * (NH * NB));
            float4* d2 = ((float4*)sAct) + 2056;
            for (int i = tid; i < 4096; i += 256) cp_async16(d2 + i, s2 + i);
            asm volatile("cp.async.commit_group;" ::: "memory");
        }
        {
            const float4* src = (const float4*)(g_hB + b2 * NH);
            float4* dst = (float4*)sh;
            if (tid < 128) dst[tid] = __ldcg(src + tid);
        }
        for (int i = tid; i < t; i += 256)
            sWrow[i] = __ldcg(&g_S[((size_t)b2 * NT + t) * NT + i]);
        __syncthreads();
        // gate scalar g = sigmoid(h . W_g + b_g)
        float pg = sh[tid] * __ldg(&W_g[tid]) + sh[tid + 256] * __ldg(&W_g[tid + 256]);
#pragma unroll
        for (int o = 16; o; o >>= 1) pg += __shfl_xor_sync(~0u, pg, o);
        if ((tid & 31) == 0) redk[tid >> 5] = pg;
        __syncthreads();
        if (tid == 0) {
            float s = 0.f;
            for (int i = 0; i < 8; i++) s += redk[i];
            sgm[0] = sigmf(s + __ldg(&b_g[0]));
        }
        __syncthreads();
        float gv = sgm[0];
        // key_w = h . W_key from register-resident half2 slice (4 chains)
        float ka[4] = {0.f, 0.f, 0.f, 0.f};
        {
            const float* shq = sh + qq * 128;
#pragma unroll
            for (int i = 0; i < 64; ++i) {
                __half2 hw = *(__half2*)&wk2[i];
                float2 wf = __half22float2(hw);
                ka[2 * (i & 1)]     += shq[2 * i]     * wf.x;
                ka[2 * (i & 1) + 1] += shq[2 * i + 1] * wf.y;
            }
        }
        float kacc = (ka[0] + ka[1]) + (ka[2] + ka[3]);
        __syncthreads();
        redk[kl * 5 + qq] = kacc;
        __syncthreads();
        if (tid < 64) {
            float kw = redk[tid * 5] + redk[tid * 5 + 1] + redk[tid * 5 + 2] + redk[tid * 5 + 3]
                     + __ldg(&b_key[k0 + tid]);
            sMk[t * 64 + tid] = __float2half_rn(kw);
        }
        // attention readout from fp16 smem Mk (4 chains)
        float aacc;
        {
            float a0 = 0.f, a1 = 0.f, a2 = 0.f, a3 = 0.f;
            const __half* mkp = sMk + kl;
            int t2 = qq;
            for (; t2 + 12 < t; t2 += 16) {
                a0 += sWrow[t2]      * __half2float(mkp[t2 * 64]);
                a1 += sWrow[t2 + 4]  * __half2float(mkp[(t2 + 4) * 64]);
                a2 += sWrow[t2 + 8]  * __half2float(mkp[(t2 + 8) * 64]);
                a3 += sWrow[t2 + 12] * __half2float(mkp[(t2 + 12) * 64]);
            }
            for (; t2 < t; t2 += 4)
                a0 += sWrow[t2] * __half2float(mkp[t2 * 64]);
            aacc = (a0 + a1) + (a2 + a3);
        }
        __syncthreads();
        redk[kl * 5 + qq] = aacc;
        __syncthreads();
        if (tid < 64) {
            float kr = (t > 0)
                ? gv * (redk[tid * 5] + redk[tid * 5 + 1] + redk[tid * 5 + 2] + redk[tid * 5 + 3])
                : 0.f;
            __stcg(&g_keyrT[(k0 + tid) * NB + b2], kr);
        }
        if (tid == 64 && kq == 0) {
            float kr = (t > 0) ? gv * __ldg(&g_wc[b2 * NT + t]) : 0.f;
            __stcg(&g_keyrT[NK * NB + b2], kr);
        }
        grid_bar(++gen);
    }
}

// ---------------- launch ---------------------------------------------------
extern "C" void kernel_launch(void* const* d_in, const int* in_sizes, int n_in,
                              void* d_out, int out_size) {
    const float* x      = (const float*)d_in[0];
    const float* W_x    = (const float*)d_in[1];
    const float* W_h    = (const float*)d_in[2];
    const float* b_lstm = (const float*)d_in[3];
    const float* W_key  = (const float*)d_in[4];
    const float* b_key  = (const float*)d_in[5];
    const float* W_g    = (const float*)d_in[6];
    const float* b_g    = (const float*)d_in[7];
    const float* cgain  = (const float*)d_in[8];
    const float* cbias  = (const float*)d_in[9];
    float* out = (float*)d_out;

    cudaFuncSetAttribute(k_rec, cudaFuncAttributeMaxDynamicSharedMemorySize,
                         SM_FLOATS * (int)sizeof(float));

    k_pack<<<(NPACK + 255) / 256, 256>>>(W_x, W_h);
    k_gram<<<NB * 36, 256>>>(x);
    k_softmax<<<NB * NT, 128>>>(cgain, cbias);
    k_rec<<<NCTA, 256, SM_FLOATS * (int)sizeof(float)>>>(b_lstm, W_key, b_key, W_g, b_g, out);
}